// round 2
// baseline (speedup 1.0000x reference)
#include <cuda_runtime.h>
#include <cuda_bf16.h>
#include <cstdint>

// LightGraphConv: out[n,:] = ci[n] * sum_{e: dst[e]==n} src_feats[src[e],:] * cj[src[e]]
// N=100000, E=1600000, D=32.
//
// Strategy: counting-sort CSR by dst, then register-accumulating pull-gather.
// Eliminates ~205MB of L2 atomic-write traffic vs the push-scatter version.

#define MAXN 100000
#define MAXE 1600000
#define SCAN_BLK 1024
#define MAX_NB ((MAXN + SCAN_BLK - 1) / SCAN_BLK)   // 98

__device__ int    g_cnt[MAXN];        // per-dst degree histogram
__device__ int    g_end[MAXN];        // exclusive scan -> fill cursors -> end pointers
__device__ int    g_bsum[MAX_NB];     // block sums for scan
__device__ int    g_boff[MAX_NB];     // scanned block offsets
__device__ int    g_esrc[MAXE];       // CSR edge payload: src node id
__device__ float4 g_wf[MAXN * 8];     // prescaled features: feats * cj

// --- pass 0: zero histogram -------------------------------------------------
__global__ void k_zero(int n) {
    int i = blockIdx.x * blockDim.x + threadIdx.x;
    if (i < n) g_cnt[i] = 0;
}

// --- pass 1: wfeats = feats * cj ---------------------------------------------
__global__ void k_prescale(const float4* __restrict__ feats4,
                           const float*  __restrict__ cj, int n) {
    int gid = blockIdx.x * blockDim.x + threadIdx.x;  // n*8 + c
    int node = gid >> 3;
    if (node >= n) return;
    float w = __ldg(cj + node);
    float4 v = __ldg(feats4 + gid);
    v.x *= w; v.y *= w; v.z *= w; v.w *= w;
    g_wf[gid] = v;
}

// --- pass 2: degree histogram -------------------------------------------------
__global__ void k_count(const int* __restrict__ dst, int e) {
    int i = blockIdx.x * blockDim.x + threadIdx.x;
    if (i < e) atomicAdd(&g_cnt[dst[i]], 1);
}

// --- pass 3a: per-block exclusive scan ----------------------------------------
__global__ void k_scan1(int n) {
    __shared__ int sh[SCAN_BLK];
    int i = blockIdx.x * SCAN_BLK + threadIdx.x;
    int v = (i < n) ? g_cnt[i] : 0;
    sh[threadIdx.x] = v;
    __syncthreads();
#pragma unroll
    for (int off = 1; off < SCAN_BLK; off <<= 1) {
        int t = (threadIdx.x >= off) ? sh[threadIdx.x - off] : 0;
        __syncthreads();
        sh[threadIdx.x] += t;
        __syncthreads();
    }
    int incl = sh[threadIdx.x];
    if (i < n) g_end[i] = incl - v;                 // exclusive within block
    if (threadIdx.x == SCAN_BLK - 1) g_bsum[blockIdx.x] = incl;
}

// --- pass 3b: scan the 98 block sums (single thread; trivial) ------------------
__global__ void k_scan2(int nb) {
    if (threadIdx.x == 0 && blockIdx.x == 0) {
        int acc = 0;
        for (int b = 0; b < nb; b++) {
            g_boff[b] = acc;
            acc += g_bsum[b];
        }
    }
}

// --- pass 3c: add block offsets ------------------------------------------------
__global__ void k_scan3(int n) {
    int i = blockIdx.x * SCAN_BLK + threadIdx.x;
    if (i < n) g_end[i] += g_boff[blockIdx.x];
}

// --- pass 4: fill CSR (cursors advance; afterwards g_end[n] = end pointer) -----
__global__ void k_fill(const int* __restrict__ src,
                       const int* __restrict__ dst, int e) {
    int i = blockIdx.x * blockDim.x + threadIdx.x;
    if (i >= e) return;
    int d = dst[i];
    int pos = atomicAdd(&g_end[d], 1);
    g_esrc[pos] = src[i];
}

// --- pass 5: pull-gather, 8 lanes per node --------------------------------------
__global__ void k_gather(const float* __restrict__ ci,
                         float4* __restrict__ out4, int n) {
    int gid = blockIdx.x * blockDim.x + threadIdx.x;
    int node = gid >> 3;
    int c = gid & 7;
    if (node >= n) return;

    int beg = (node == 0) ? 0 : __ldg(&g_end[node - 1]);
    int stop = __ldg(&g_end[node]);

    float4 acc = make_float4(0.f, 0.f, 0.f, 0.f);
#pragma unroll 2
    for (int e = beg; e < stop; e++) {
        int s = __ldg(&g_esrc[e]);
        float4 v = __ldg(&g_wf[s * 8 + c]);
        acc.x += v.x; acc.y += v.y; acc.z += v.z; acc.w += v.w;
    }
    float sc = __ldg(ci + node);
    acc.x *= sc; acc.y *= sc; acc.z *= sc; acc.w *= sc;
    out4[gid] = acc;
}

extern "C" void kernel_launch(void* const* d_in, const int* in_sizes, int n_in,
                              void* d_out, int out_size)
{
    const float* src_feats = (const float*)d_in[0];   // [N, 32]
    const float* cj        = (const float*)d_in[1];   // [N]
    const float* ci        = (const float*)d_in[2];   // [N]
    const int*   src_idx   = (const int*)  d_in[3];   // [E]
    const int*   dst_idx   = (const int*)  d_in[4];   // [E]
    float*       out       = (float*)d_out;           // [N, 32]

    const int N = in_sizes[1];
    const int E = in_sizes[3];
    const int NB = (N + SCAN_BLK - 1) / SCAN_BLK;

    const int T = 256;

    k_zero<<<(N + T - 1) / T, T>>>(N);
    k_prescale<<<((long long)N * 8 + T - 1) / T, T>>>((const float4*)src_feats, cj, N);
    k_count<<<(E + T - 1) / T, T>>>(dst_idx, E);
    k_scan1<<<NB, SCAN_BLK>>>(N);
    k_scan2<<<1, 32>>>(NB);
    k_scan3<<<NB, SCAN_BLK>>>(N);
    k_fill<<<(E + T - 1) / T, T>>>(src_idx, dst_idx, E);
    k_gather<<<((long long)N * 8 + T - 1) / T, T>>>(ci, (float4*)out, N);
}

// round 3
// speedup vs baseline: 1.2911x; 1.2911x over previous
#include <cuda_runtime.h>
#include <cuda_fp16.h>
#include <cuda_bf16.h>
#include <cstdint>

// LightGraphConv: out[n,:] = ci[n] * sum_{e: dst[e]==n} src_feats[src[e],:] * cj[src[e]]
// N=100000, E=1600000, D=32.
//
// Strategy (v3): L2-resident atomic scatter with byte-dieting.
//  - Prescale feats*cj once into packed fp16 (halves the per-edge gather read:
//    205MB -> 102MB of L2 traffic); accumulation stays fp32 via red.v4.f32.
//  - ci fused into the scatter message (linear), deleting the epilogue pass.

#define MAXN 100000

__device__ uint2 g_wfh[MAXN * 8];   // [N][8] x (4 halves) = packed feats*cj rows (64B/row)

// --- pass 1: pack wf = half(feats * cj) ---------------------------------------
__global__ void k_prescale(const float4* __restrict__ feats4,
                           const float*  __restrict__ cj, int n) {
    int gid = blockIdx.x * blockDim.x + threadIdx.x;   // node*8 + c
    int node = gid >> 3;
    if (node >= n) return;
    float w = __ldg(cj + node);
    float4 v = __ldg(feats4 + gid);
    half2 lo = __floats2half2_rn(v.x * w, v.y * w);
    half2 hi = __floats2half2_rn(v.z * w, v.w * w);
    uint2 p;
    p.x = *reinterpret_cast<uint32_t*>(&lo);
    p.y = *reinterpret_cast<uint32_t*>(&hi);
    g_wfh[gid] = p;
}

// --- pass 2: edge scatter, 8 lanes/edge, fp32 vector reductions, ci fused ------
__global__ void lgc_scatter_kernel(const float* __restrict__ ci,
                                   const int*   __restrict__ src,
                                   const int*   __restrict__ dst,
                                   float4*      __restrict__ out4,
                                   int n_edges)
{
    int gid = blockIdx.x * blockDim.x + threadIdx.x;
    int e = gid >> 3;          // edge index
    int c = gid & 7;           // 4-half chunk within the 32-elem row
    if (e >= n_edges) return;

    int s = __ldg(src + e);
    int d = __ldg(dst + e);
    float sc = __ldg(ci + d);

    uint2 p = __ldg(&g_wfh[s * 8 + c]);
    half2 lo = *reinterpret_cast<half2*>(&p.x);
    half2 hi = *reinterpret_cast<half2*>(&p.y);
    float2 a = __half22float2(lo);
    float2 b = __half22float2(hi);

    float4 v;
    v.x = a.x * sc; v.y = a.y * sc; v.z = b.x * sc; v.w = b.y * sc;

    float4* pd = out4 + (long long)d * 8 + c;
    asm volatile("red.global.add.v4.f32 [%0], {%1, %2, %3, %4};"
                 :: "l"(pd), "f"(v.x), "f"(v.y), "f"(v.z), "f"(v.w)
                 : "memory");
}

extern "C" void kernel_launch(void* const* d_in, const int* in_sizes, int n_in,
                              void* d_out, int out_size)
{
    const float* src_feats = (const float*)d_in[0];   // [N, 32]
    const float* cj        = (const float*)d_in[1];   // [N]
    const float* ci        = (const float*)d_in[2];   // [N]
    const int*   src_idx   = (const int*)  d_in[3];   // [E]
    const int*   dst_idx   = (const int*)  d_in[4];   // [E]
    float*       out       = (float*)d_out;           // [N, 32]

    const int N = in_sizes[1];
    const int E = in_sizes[3];
    const int T = 256;

    // Zero the accumulator (independent of prescale; both precede the scatter).
    cudaMemsetAsync(d_out, 0, (size_t)out_size * sizeof(float));

    k_prescale<<<(int)(((long long)N * 8 + T - 1) / T), T>>>(
        (const float4*)src_feats, cj, N);

    lgc_scatter_kernel<<<(int)(((long long)E * 8 + T - 1) / T), T>>>(
        ci, src_idx, dst_idx, (float4*)out, E);
}